// round 3
// baseline (speedup 1.0000x reference)
#include <cuda_runtime.h>
#include <cuda_bf16.h>
#include <math.h>

// ---------------- problem constants ----------------
#define Nn     64000       // nodes
#define NPG    500         // nodes per graph
#define Gg     128         // graphs
#define Ee     131072      // edges
#define DIN    768
#define Hh     512
#define Cc     4
#define Kk     250         // kept per graph
#define EPSBN  1e-5f

// ---------------- device scratch (no allocs allowed) ----------------
__device__ float g_h [(size_t)Nn * Hh];   // x @ gcn_w   (pre-aggregation)
__device__ float g_hr[(size_t)Nn * Hh];   // relu(aggregated)
__device__ float g_dinv[Nn];
__device__ int   g_cnt[Nn];
__device__ int   g_offs[Nn + 1];
__device__ int   g_cursor[Nn];
__device__ int   g_csrc[Ee];
__device__ float g_ccoef[Ee];
__device__ float g_t1[Nn];
__device__ float g_t2[Nn];
__device__ float g_score[Nn];
__device__ int   g_sel [Gg * Kk];
__device__ float g_selw[Gg * Kk];
__device__ float g_S [Gg * Hh];
__device__ float g_Qg[Gg * Hh];   // per-graph sum of squares (deterministic)
__device__ float g_A[Hh];         // BN fused scale  (rstd*gamma/K)
__device__ float g_B[Hh];         // BN fused shift  (beta - mu*rstd*gamma)
__device__ int   g_e64;           // 1 if index inputs are int64, 0 if int32

// ---------------- index dtype probe ----------------
// batch[i] = i / 500. If stored as int32, word[500] == batch[500] == 1.
// If stored as int64, word[500] is the LOW word of batch[250] == 0.
__global__ void k_detect(const int* __restrict__ batch_words) {
    g_e64 = (batch_words[500] == 1) ? 0 : 1;
}

__device__ __forceinline__ int edge_at(const void* ei, int pos) {
    if (g_e64) return (int)((const long long*)ei)[pos];
    return ((const int*)ei)[pos];
}

// ---------------- small kernels ----------------
__global__ void k_init() {
    int i = blockIdx.x * blockDim.x + threadIdx.x;
    if (i < Nn) g_cnt[i] = 0;
}

__global__ void k_count(const void* __restrict__ ei) {
    int e = blockIdx.x * blockDim.x + threadIdx.x;
    if (e >= Ee) return;
    int d = edge_at(ei, Ee + e);
    atomicAdd(&g_cnt[d], 1);
}

__global__ void k_dinv() {
    int i = blockIdx.x * blockDim.x + threadIdx.x;
    if (i >= Nn) return;
    g_dinv[i] = rsqrtf(1.0f + (float)g_cnt[i]);   // self-loop adds 1
}

// exclusive prefix sum of g_cnt -> g_offs, g_cursor; single block of 1024
__global__ void k_scan() {
    __shared__ int warpsum[32];
    __shared__ int carry_s;
    int tid = threadIdx.x, lane = tid & 31, wid = tid >> 5;
    if (tid == 0) carry_s = 0;
    __syncthreads();
    for (int base = 0; base < Nn; base += 1024) {
        int idx = base + tid;
        int v = (idx < Nn) ? g_cnt[idx] : 0;
        int x = v;
        #pragma unroll
        for (int o = 1; o < 32; o <<= 1) { int y = __shfl_up_sync(~0u, x, o); if (lane >= o) x += y; }
        if (lane == 31) warpsum[wid] = x;
        __syncthreads();
        if (wid == 0) {
            int w = warpsum[lane];
            #pragma unroll
            for (int o = 1; o < 32; o <<= 1) { int y = __shfl_up_sync(~0u, w, o); if (lane >= o) w += y; }
            warpsum[lane] = w;
        }
        __syncthreads();
        int pre   = (wid > 0) ? warpsum[wid - 1] : 0;
        int incl  = x + pre;
        int carry = carry_s;
        if (idx < Nn) { int ex = carry + incl - v; g_offs[idx] = ex; g_cursor[idx] = ex; }
        __syncthreads();
        if (tid == 1023) carry_s = carry + incl;
        __syncthreads();
    }
    if (tid == 0) g_offs[Nn] = carry_s;
}

__global__ void k_fill(const void* __restrict__ ei) {
    int e = blockIdx.x * blockDim.x + threadIdx.x;
    if (e >= Ee) return;
    int s = edge_at(ei, e);
    int d = edge_at(ei, Ee + e);
    int p = atomicAdd(&g_cursor[d], 1);
    g_csrc[p]  = s;
    g_ccoef[p] = g_dinv[s] * g_dinv[d];
}

// ---------------- GEMM: g_h = x @ gcn_w  (M=64000, K=768, N=512) ----------------
// 128x128 tile, BK=8, double-buffered smem, 1 barrier per K-tile.
__global__ __launch_bounds__(256) void k_gemm(const float* __restrict__ A,
                                              const float* __restrict__ Bw) {
    __shared__ float As[2][8 * 128];
    __shared__ float Bs[2][8 * 128];
    const int tid = threadIdx.x;
    const float* Ab = A   + (size_t)blockIdx.y * 128 * DIN;
    const float* Bb = Bw  + blockIdx.x * 128;
    float*       Cb = g_h + (size_t)blockIdx.y * 128 * Hh + blockIdx.x * 128;

    const int aRow = tid >> 1, aCol = (tid & 1) * 4;   // A: 128x8 tile
    const int bRow = tid >> 5, bCol = (tid & 31) * 4;  // B: 8x128 tile
    const int tr = tid >> 4, tc = tid & 15;

    float acc[8][8];
    #pragma unroll
    for (int i = 0; i < 8; i++)
        #pragma unroll
        for (int j = 0; j < 8; j++) acc[i][j] = 0.0f;

    // preload tile 0 into buffer 0
    float4 pa = *(const float4*)(Ab + (size_t)aRow * DIN + aCol);
    float4 pb = *(const float4*)(Bb + (size_t)bRow * Hh + bCol);
    As[0][(aCol + 0) * 128 + aRow] = pa.x;
    As[0][(aCol + 1) * 128 + aRow] = pa.y;
    As[0][(aCol + 2) * 128 + aRow] = pa.z;
    As[0][(aCol + 3) * 128 + aRow] = pa.w;
    *(float4*)(&Bs[0][bRow * 128 + bCol]) = pb;
    __syncthreads();

    const int NT = DIN / 8;   // 96 tiles
    #pragma unroll 1
    for (int t = 0; t < NT; t++) {
        int cur = t & 1, nxt = cur ^ 1;
        // prefetch next tile into registers (hides LDG under compute)
        if (t + 1 < NT) {
            int k0 = (t + 1) * 8;
            pa = *(const float4*)(Ab + (size_t)aRow * DIN + k0 + aCol);
            pb = *(const float4*)(Bb + (size_t)(k0 + bRow) * Hh + bCol);
        }
        #pragma unroll
        for (int k = 0; k < 8; k++) {
            float4 m0 = *(const float4*)(&As[cur][k * 128 + tr * 8]);
            float4 m1 = *(const float4*)(&As[cur][k * 128 + tr * 8 + 4]);
            float4 n0 = *(const float4*)(&Bs[cur][k * 128 + tc * 8]);
            float4 n1 = *(const float4*)(&Bs[cur][k * 128 + tc * 8 + 4]);
            float rm[8] = {m0.x, m0.y, m0.z, m0.w, m1.x, m1.y, m1.z, m1.w};
            float rn[8] = {n0.x, n0.y, n0.z, n0.w, n1.x, n1.y, n1.z, n1.w};
            #pragma unroll
            for (int i = 0; i < 8; i++)
                #pragma unroll
                for (int j = 0; j < 8; j++) acc[i][j] += rm[i] * rn[j];
        }
        if (t + 1 < NT) {
            As[nxt][(aCol + 0) * 128 + aRow] = pa.x;
            As[nxt][(aCol + 1) * 128 + aRow] = pa.y;
            As[nxt][(aCol + 2) * 128 + aRow] = pa.z;
            As[nxt][(aCol + 3) * 128 + aRow] = pa.w;
            *(float4*)(&Bs[nxt][bRow * 128 + bCol]) = pb;
        }
        __syncthreads();
    }

    #pragma unroll
    for (int i = 0; i < 8; i++) {
        #pragma unroll
        for (int j = 0; j < 8; j += 4) {
            *(float4*)(Cb + (size_t)(tr * 8 + i) * Hh + tc * 8 + j) =
                make_float4(acc[i][j], acc[i][j+1], acc[i][j+2], acc[i][j+3]);
        }
    }
}

// ---------------- aggregation + relu + SAG dots (warp per node) ----------------
__global__ __launch_bounds__(256) void k_agg(const float* __restrict__ bias,
                                             const float* __restrict__ w1,
                                             const float* __restrict__ w2) {
    int warp = (blockIdx.x * blockDim.x + threadIdx.x) >> 5;
    int lane = threadIdx.x & 31;
    if (warp >= Nn) return;
    const int i = warp;
    float di  = g_dinv[i];
    float dii = di * di;

    const float4* hrow = (const float4*)(g_h + (size_t)i * Hh);
    const float4* brow = (const float4*)bias;
    float4 acc[4];
    #pragma unroll
    for (int j = 0; j < 4; j++) {
        float4 a = hrow[lane + 32 * j];
        float4 b = brow[lane + 32 * j];
        acc[j] = make_float4(a.x * dii + b.x, a.y * dii + b.y,
                             a.z * dii + b.z, a.w * dii + b.w);
    }
    int e0 = g_offs[i], e1 = g_offs[i + 1];
    for (int p = e0; p < e1; p++) {
        int   s  = g_csrc[p];
        float cf = g_ccoef[p];
        const float4* srow = (const float4*)(g_h + (size_t)s * Hh);
        #pragma unroll
        for (int j = 0; j < 4; j++) {
            float4 v = srow[lane + 32 * j];
            acc[j].x += v.x * cf; acc[j].y += v.y * cf;
            acc[j].z += v.z * cf; acc[j].w += v.w * cf;
        }
    }
    const float4* w1v = (const float4*)w1;
    const float4* w2v = (const float4*)w2;
    float4* orow = (float4*)(g_hr + (size_t)i * Hh);
    float p1 = 0.0f, p2 = 0.0f;
    #pragma unroll
    for (int j = 0; j < 4; j++) {
        acc[j].x = fmaxf(acc[j].x, 0.0f); acc[j].y = fmaxf(acc[j].y, 0.0f);
        acc[j].z = fmaxf(acc[j].z, 0.0f); acc[j].w = fmaxf(acc[j].w, 0.0f);
        orow[lane + 32 * j] = acc[j];
        float4 a = w1v[lane + 32 * j];
        float4 c = w2v[lane + 32 * j];
        p1 += acc[j].x * a.x + acc[j].y * a.y + acc[j].z * a.z + acc[j].w * a.w;
        p2 += acc[j].x * c.x + acc[j].y * c.y + acc[j].z * c.z + acc[j].w * c.w;
    }
    #pragma unroll
    for (int o = 16; o > 0; o >>= 1) {
        p1 += __shfl_down_sync(~0u, p1, o);
        p2 += __shfl_down_sync(~0u, p2, o);
    }
    if (lane == 0) { g_t1[i] = p1; g_t2[i] = p2; }
}

// ---------------- SAG score: s = t1[i] + b + sum_{src->i} t2[src] ----------------
__global__ void k_score(const float* __restrict__ sagb) {
    int i = blockIdx.x * blockDim.x + threadIdx.x;
    if (i >= Nn) return;
    float s = g_t1[i] + sagb[0];
    int e0 = g_offs[i], e1 = g_offs[i + 1];
    for (int p = e0; p < e1; p++) s += g_t2[g_csrc[p]];
    g_score[i] = s;
}

// ---------------- per-graph top-k via bitonic sort of 512 ----------------
__global__ __launch_bounds__(256) void k_topk() {
    __shared__ float sv[512];
    __shared__ int   si[512];
    int g = blockIdx.x, tid = threadIdx.x;
    #pragma unroll
    for (int t = tid; t < 512; t += 256) {
        if (t < NPG) { sv[t] = g_score[g * NPG + t]; si[t] = t; }
        else         { sv[t] = -INFINITY;            si[t] = -1; }
    }
    __syncthreads();
    // ascending bitonic sort; top Kk end up at [512-Kk, 512)
    for (int k = 2; k <= 512; k <<= 1) {
        for (int j = k >> 1; j > 0; j >>= 1) {
            #pragma unroll
            for (int t = tid; t < 512; t += 256) {
                int l = t ^ j;
                if (l > t) {
                    bool up = ((t & k) == 0);
                    float a = sv[t], b = sv[l];
                    if ((up && a > b) || (!up && a < b)) {
                        sv[t] = b; sv[l] = a;
                        int ia = si[t]; si[t] = si[l]; si[l] = ia;
                    }
                }
            }
            __syncthreads();
        }
    }
    if (tid < Kk) {
        int pos = 512 - Kk + tid;
        g_sel [g * Kk + tid] = g * NPG + si[pos];
        g_selw[g * Kk + tid] = tanhf(sv[pos]);
    }
}

// ---------------- per-graph column sums S_g and sum-of-squares Q_g ----------------
__global__ __launch_bounds__(256) void k_pool() {
    __shared__ int   ssel[Kk];
    __shared__ float ssw [Kk];
    int g = blockIdx.x, t = threadIdx.x;
    for (int p = t; p < Kk; p += 256) {
        ssel[p] = g_sel [g * Kk + p];
        ssw [p] = g_selw[g * Kk + p];
    }
    __syncthreads();
    float a0 = 0, a1 = 0, q0 = 0, q1 = 0;
    for (int p = 0; p < Kk; p++) {
        const float* row = g_hr + (size_t)ssel[p] * Hh;
        float w  = ssw[p];
        float v0 = row[t]       * w;
        float v1 = row[t + 256] * w;
        a0 += v0; a1 += v1; q0 += v0 * v0; q1 += v1 * v1;
    }
    g_S [g * Hh + t]       = a0;
    g_S [g * Hh + t + 256] = a1;
    g_Qg[g * Hh + t]       = q0;
    g_Qg[g * Hh + t + 256] = q1;
}

// ---------------- BN stats fused into scale/shift (deterministic) ----------------
__global__ void k_stats(const float* __restrict__ gamma, const float* __restrict__ beta) {
    int c = threadIdx.x;      // 512 threads
    float sm = 0.0f, sq = 0.0f;
    for (int g = 0; g < Gg; g++) {
        sm += g_S [g * Hh + c];
        sq += g_Qg[g * Hh + c];
    }
    const float inv = 1.0f / (float)(Gg * Kk);
    float mu   = sm * inv;
    float var  = sq * inv - mu * mu;
    float rstd = rsqrtf(var + EPSBN);
    float sc   = rstd * gamma[c];
    g_A[c] = sc * (1.0f / (float)Kk);
    g_B[c] = beta[c] - mu * sc;
}

// ---------------- fused pooled -> fc -> log_softmax ----------------
__global__ __launch_bounds__(128) void k_final(const float* __restrict__ fcw,
                                               const float* __restrict__ fcb,
                                               float* __restrict__ out) {
    int g = blockIdx.x, t = threadIdx.x;   // 128 threads
    float lg[4] = {0, 0, 0, 0};
    for (int c = t; c < Hh; c += 128) {
        float p  = g_S[g * Hh + c] * g_A[c] + g_B[c];  // pooled[g][c]
        float4 w = *(const float4*)(fcw + c * Cc);
        lg[0] += p * w.x; lg[1] += p * w.y; lg[2] += p * w.z; lg[3] += p * w.w;
    }
    #pragma unroll
    for (int o = 16; o > 0; o >>= 1)
        #pragma unroll
        for (int k = 0; k < 4; k++) lg[k] += __shfl_down_sync(~0u, lg[k], o);
    __shared__ float sm[4][4];
    int lane = t & 31, w = t >> 5;
    if (lane == 0) { sm[w][0]=lg[0]; sm[w][1]=lg[1]; sm[w][2]=lg[2]; sm[w][3]=lg[3]; }
    __syncthreads();
    if (t == 0) {
        float l[4];
        #pragma unroll
        for (int k = 0; k < 4; k++)
            l[k] = sm[0][k] + sm[1][k] + sm[2][k] + sm[3][k] + fcb[k];
        float m = fmaxf(fmaxf(l[0], l[1]), fmaxf(l[2], l[3]));
        float s = 0.0f;
        #pragma unroll
        for (int k = 0; k < 4; k++) s += expf(l[k] - m);
        float lse = logf(s);
        #pragma unroll
        for (int k = 0; k < 4; k++) out[g * Cc + k] = l[k] - m - lse;
    }
}

// ---------------- launcher ----------------
extern "C" void kernel_launch(void* const* d_in, const int* in_sizes, int n_in,
                              void* d_out, int out_size) {
    const float* x     = (const float*)d_in[0];
    const float* gcnw  = (const float*)d_in[1];
    const float* gcnb  = (const float*)d_in[2];
    const float* sagw1 = (const float*)d_in[3];
    const float* sagw2 = (const float*)d_in[4];
    const float* sagb  = (const float*)d_in[5];
    const float* bngam = (const float*)d_in[6];
    const float* bnbet = (const float*)d_in[7];
    const float* fcw   = (const float*)d_in[8];
    const float* fcb   = (const float*)d_in[9];
    const void*  ei    = d_in[10];
    const int*   batw  = (const int*)d_in[11];
    float*       out   = (float*)d_out;

    k_detect<<<1, 1>>>(batw);
    k_init <<<(Nn + 255) / 256, 256>>>();
    k_count<<<(Ee + 255) / 256, 256>>>(ei);
    k_dinv <<<(Nn + 255) / 256, 256>>>();
    k_scan <<<1, 1024>>>();
    k_fill <<<(Ee + 255) / 256, 256>>>(ei);

    { dim3 grid(Hh / 128, Nn / 128);
      k_gemm<<<grid, 256>>>(x, gcnw); }

    k_agg  <<<(Nn * 32 + 255) / 256, 256>>>(gcnb, sagw1, sagw2);
    k_score<<<(Nn + 255) / 256, 256>>>(sagb);
    k_topk <<<Gg, 256>>>();
    k_pool <<<Gg, 256>>>();
    k_stats<<<1, Hh>>>(bngam, bnbet);
    k_final<<<Gg, 128>>>(fcw, fcb, out);
}

// round 7
// speedup vs baseline: 1.7666x; 1.7666x over previous
#include <cuda_runtime.h>
#include <cuda_bf16.h>
#include <math.h>
#include <stdint.h>

// ---------------- problem constants ----------------
#define Nn     64000
#define NPG    500
#define Gg     128
#define Ee     131072
#define DIN    768
#define Hh     512
#define Cc     4
#define Kk     250
#define EPSBN  1e-5f

// ---------------- device scratch ----------------
__device__ float g_h [(size_t)Nn * Hh];
__device__ float g_hr[(size_t)Nn * Hh];
__device__ float g_dinv[Nn];
__device__ int   g_cnt[Nn];
__device__ int   g_offs[Nn + 1];
__device__ int   g_cursor[Nn];
__device__ int   g_csrc[Ee];
__device__ float g_ccoef[Ee];
__device__ float g_t1[Nn];
__device__ float g_t2[Nn];
__device__ float g_score[Nn];
__device__ int   g_sel [Gg * Kk];
__device__ float g_selw[Gg * Kk];
__device__ float g_S [Gg * Hh];
__device__ float g_Qg[Gg * Hh];
__device__ float g_A[Hh];
__device__ float g_B[Hh];
__device__ int   g_e64;
// bf16 split operands: A [m][k] row-major; B stored [n][k] (k-contiguous)
__device__ __align__(16) unsigned short g_ahi[(size_t)Nn * DIN];
__device__ __align__(16) unsigned short g_alo[(size_t)Nn * DIN];
__device__ __align__(16) unsigned short g_bhi[(size_t)Hh * DIN];
__device__ __align__(16) unsigned short g_blo[(size_t)Hh * DIN];

// ---------------- helpers ----------------
__device__ __forceinline__ uint32_t smem_u32(const void* p) {
    uint32_t a;
    asm("{ .reg .u64 t; cvta.to.shared.u64 t, %1; cvt.u32.u64 %0, t; }" : "=r"(a) : "l"(p));
    return a;
}
__device__ __forceinline__ void cpasync16(uint32_t d, const void* s) {
    asm volatile("cp.async.cg.shared.global [%0], [%1], 16;" :: "r"(d), "l"(s) : "memory");
}
#define CP_COMMIT() asm volatile("cp.async.commit_group;" ::: "memory")
#define CP_WAIT(n)  asm volatile("cp.async.wait_group %0;" :: "n"(n) : "memory")

__device__ __forceinline__ void mma_bf16(float* c, const uint32_t* a, const uint32_t* b) {
    asm volatile(
        "mma.sync.aligned.m16n8k16.row.col.f32.bf16.bf16.f32 "
        "{%0,%1,%2,%3},{%4,%5,%6,%7},{%8,%9},{%0,%1,%2,%3};"
        : "+f"(c[0]), "+f"(c[1]), "+f"(c[2]), "+f"(c[3])
        : "r"(a[0]), "r"(a[1]), "r"(a[2]), "r"(a[3]), "r"(b[0]), "r"(b[1]));
}

// ---------------- dtype probe ----------------
// batch[i] = i / 500. If stored as int32, word[500] == 1; if int64, word 500
// is the low half of batch[250] == 0.
__global__ void k_detect(const int* __restrict__ batch_words) {
    g_e64 = (batch_words[500] == 1) ? 0 : 1;
}
__device__ __forceinline__ int edge_at(const void* ei, int pos) {
    if (g_e64) return (int)((const long long*)ei)[pos];
    return ((const int*)ei)[pos];
}

// ---------------- edge pipeline ----------------
__global__ void k_init() {
    int i = blockIdx.x * blockDim.x + threadIdx.x;
    if (i < Nn) g_cnt[i] = 0;
}
__global__ void k_count(const void* __restrict__ ei) {
    int e = blockIdx.x * blockDim.x + threadIdx.x;
    if (e >= Ee) return;
    atomicAdd(&g_cnt[edge_at(ei, Ee + e)], 1);
}
__global__ void k_dinv() {
    int i = blockIdx.x * blockDim.x + threadIdx.x;
    if (i >= Nn) return;
    g_dinv[i] = rsqrtf(1.0f + (float)g_cnt[i]);
}
__global__ void k_scan() {
    __shared__ int warpsum[32];
    __shared__ int carry_s;
    int tid = threadIdx.x, lane = tid & 31, wid = tid >> 5;
    if (tid == 0) carry_s = 0;
    __syncthreads();
    for (int base = 0; base < Nn; base += 1024) {
        int idx = base + tid;
        int v = (idx < Nn) ? g_cnt[idx] : 0;
        int x = v;
        #pragma unroll
        for (int o = 1; o < 32; o <<= 1) { int y = __shfl_up_sync(~0u, x, o); if (lane >= o) x += y; }
        if (lane == 31) warpsum[wid] = x;
        __syncthreads();
        if (wid == 0) {
            int w = warpsum[lane];
            #pragma unroll
            for (int o = 1; o < 32; o <<= 1) { int y = __shfl_up_sync(~0u, w, o); if (lane >= o) w += y; }
            warpsum[lane] = w;
        }
        __syncthreads();
        int pre = (wid > 0) ? warpsum[wid - 1] : 0;
        int incl = x + pre;
        int carry = carry_s;
        if (idx < Nn) { int ex = carry + incl - v; g_offs[idx] = ex; g_cursor[idx] = ex; }
        __syncthreads();
        if (tid == 1023) carry_s = carry + incl;
        __syncthreads();
    }
    if (tid == 0) g_offs[Nn] = carry_s;
}
__global__ void k_fill(const void* __restrict__ ei) {
    int e = blockIdx.x * blockDim.x + threadIdx.x;
    if (e >= Ee) return;
    int s = edge_at(ei, e);
    int d = edge_at(ei, Ee + e);
    int p = atomicAdd(&g_cursor[d], 1);
    g_csrc[p]  = s;
    g_ccoef[p] = g_dinv[s] * g_dinv[d];
}

// ---------------- A conversion: fp32 -> bf16 hi/lo ----------------
__global__ __launch_bounds__(256) void k_conv_a(const float* __restrict__ x) {
    size_t i = (size_t)blockIdx.x * 256 + threadIdx.x;   // over Nn*DIN/4
    if (i >= (size_t)Nn * DIN / 4) return;
    float4 v = ((const float4*)x)[i];
    __nv_bfloat16 h0 = __float2bfloat16(v.x), h1 = __float2bfloat16(v.y);
    __nv_bfloat16 h2 = __float2bfloat16(v.z), h3 = __float2bfloat16(v.w);
    uint32_t hi01 = ((uint32_t)__bfloat16_as_ushort(h1) << 16) | __bfloat16_as_ushort(h0);
    uint32_t hi23 = ((uint32_t)__bfloat16_as_ushort(h3) << 16) | __bfloat16_as_ushort(h2);
    float l0 = v.x - __bfloat162float(h0), l1 = v.y - __bfloat162float(h1);
    float l2 = v.z - __bfloat162float(h2), l3 = v.w - __bfloat162float(h3);
    uint32_t lo01, lo23;
    asm("cvt.rn.bf16x2.f32 %0, %1, %2;" : "=r"(lo01) : "f"(l1), "f"(l0));
    asm("cvt.rn.bf16x2.f32 %0, %1, %2;" : "=r"(lo23) : "f"(l3), "f"(l2));
    ((uint2*)g_ahi)[i] = make_uint2(hi01, hi23);
    ((uint2*)g_alo)[i] = make_uint2(lo01, lo23);
}

// ---------------- B conversion: w[k][n] fp32 -> bhi/blo[n][k] bf16 ----------------
// Tiled transpose through shared memory: block handles 16 k x 128 n.
__global__ __launch_bounds__(256) void k_conv_b(const float* __restrict__ w) {
    __shared__ unsigned short shi[16][136];
    __shared__ unsigned short slo[16][136];
    int kb = blockIdx.y * 16;
    int nb = blockIdx.x * 128;
    int t = threadIdx.x;
    #pragma unroll
    for (int it = 0; it < 8; it++) {
        int id = t + it * 256;
        int kk = id >> 7, nn = id & 127;
        float v = w[(size_t)(kb + kk) * Hh + nb + nn];
        __nv_bfloat16 h = __float2bfloat16(v);
        shi[kk][nn] = __bfloat16_as_ushort(h);
        slo[kk][nn] = __bfloat16_as_ushort(__float2bfloat16(v - __bfloat162float(h)));
    }
    __syncthreads();
    #pragma unroll
    for (int it = 0; it < 8; it++) {
        int id = t + it * 256;
        int nn = id >> 4, kk = id & 15;
        g_bhi[(size_t)(nb + nn) * DIN + kb + kk] = shi[kk][nn];
        g_blo[(size_t)(nb + nn) * DIN + kb + kk] = slo[kk][nn];
    }
}

// ---------------- bf16 3-term GEMM via mma.sync ----------------
// CTA tile 128(M) x 256(N); warp tile 64x64; K chunks of 64, 36 chunks:
//   cc 0-11: Ahi*Bhi, 12-23: Alo*Bhi, 24-35: Ahi*Blo  (k0 = (cc%12)*64)
#define ROWB   144                 // padded row bytes (72 bf16)
#define ATILEB (128 * ROWB)        // 18432
#define BTILEB (256 * ROWB)        // 36864
#define STAGEB (ATILEB + BTILEB)   // 55296
#define MMA_SMEM (2 * STAGEB)      // 110592

__global__ __launch_bounds__(256, 1) void k_mma() {
    extern __shared__ char sm[];
    const uint32_t sb = smem_u32(sm);
    const int tid = threadIdx.x, lane = tid & 31, wid = tid >> 5;
    const int wm = wid >> 2, wn = wid & 3;      // 2 x 4 warp grid
    const int m0 = blockIdx.y * 128, n0 = blockIdx.x * 256;
    const int g = lane >> 2, ti = lane & 3;

    float acc[4][8][4];
    #pragma unroll
    for (int a = 0; a < 4; a++)
        #pragma unroll
        for (int b = 0; b < 8; b++)
            #pragma unroll
            for (int c = 0; c < 4; c++) acc[a][b][c] = 0.0f;

    auto load_cc = [&](int st, int cc) {
        int term = cc / 12;
        int k0 = (cc % 12) * 64;
        const unsigned short* Ag = (term == 1) ? g_alo : g_ahi;
        const unsigned short* Bg = (term == 2) ? g_blo : g_bhi;
        uint32_t ab = sb + st * STAGEB;
        uint32_t bb = ab + ATILEB;
        #pragma unroll
        for (int it = 0; it < 4; it++) {
            int id = tid + it * 256;
            int row = id >> 3, ch = id & 7;
            cpasync16(ab + row * ROWB + ch * 16,
                      Ag + (size_t)(m0 + row) * DIN + k0 + ch * 8);
        }
        #pragma unroll
        for (int it = 0; it < 8; it++) {
            int id = tid + it * 256;
            int row = id >> 3, ch = id & 7;
            cpasync16(bb + row * ROWB + ch * 16,
                      Bg + (size_t)(n0 + row) * DIN + k0 + ch * 8);
        }
    };

    load_cc(0, 0); CP_COMMIT();

    for (int cc = 0; cc < 36; cc++) {
        if (cc + 1 < 36) { load_cc((cc + 1) & 1, cc + 1); CP_COMMIT(); CP_WAIT(1); }
        else             { CP_WAIT(0); }
        __syncthreads();
        uint32_t ab = sb + (cc & 1) * STAGEB;
        uint32_t bb = ab + ATILEB;
        #pragma unroll
        for (int ks = 0; ks < 4; ks++) {
            const int kb = ks * 32 + ti * 4;
            uint32_t af[4][4], bf[8][2];
            #pragma unroll
            for (int mt = 0; mt < 4; mt++) {
                uint32_t r = ab + (uint32_t)(wm * 64 + mt * 16 + g) * ROWB + kb;
                asm volatile("ld.shared.b32 %0,[%1];" : "=r"(af[mt][0]) : "r"(r));
                asm volatile("ld.shared.b32 %0,[%1];" : "=r"(af[mt][1]) : "r"(r + 8 * ROWB));
                asm volatile("ld.shared.b32 %0,[%1];" : "=r"(af[mt][2]) : "r"(r + 16));
                asm volatile("ld.shared.b32 %0,[%1];" : "=r"(af[mt][3]) : "r"(r + 8 * ROWB + 16));
            }
            #pragma unroll
            for (int nt = 0; nt < 8; nt++) {
                uint32_t r = bb + (uint32_t)(wn * 64 + nt * 8 + g) * ROWB + kb;
                asm volatile("ld.shared.b32 %0,[%1];" : "=r"(bf[nt][0]) : "r"(r));
                asm volatile("ld.shared.b32 %0,[%1];" : "=r"(bf[nt][1]) : "r"(r + 16));
            }
            #pragma unroll
            for (int mt = 0; mt < 4; mt++)
                #pragma unroll
                for (int nt = 0; nt < 8; nt++)
                    mma_bf16(acc[mt][nt], af[mt], bf[nt]);
        }
        __syncthreads();
    }

    #pragma unroll
    for (int mt = 0; mt < 4; mt++) {
        int r = m0 + wm * 64 + mt * 16 + g;
        #pragma unroll
        for (int nt = 0; nt < 8; nt++) {
            int c = n0 + wn * 64 + nt * 8 + 2 * ti;
            *(float2*)&g_h[(size_t)r * Hh + c] =
                make_float2(acc[mt][nt][0], acc[mt][nt][1]);
            *(float2*)&g_h[(size_t)(r + 8) * Hh + c] =
                make_float2(acc[mt][nt][2], acc[mt][nt][3]);
        }
    }
}

// ---------------- aggregation + relu + SAG dots (warp per node) ----------------
__global__ __launch_bounds__(256) void k_agg(const float* __restrict__ bias,
                                             const float* __restrict__ w1,
                                             const float* __restrict__ w2) {
    int warp = (blockIdx.x * blockDim.x + threadIdx.x) >> 5;
    int lane = threadIdx.x & 31;
    if (warp >= Nn) return;
    const int i = warp;
    float di = g_dinv[i];
    float dii = di * di;

    const float4* hrow = (const float4*)(g_h + (size_t)i * Hh);
    const float4* brow = (const float4*)bias;
    float4 acc[4];
    #pragma unroll
    for (int j = 0; j < 4; j++) {
        float4 a = hrow[lane + 32 * j];
        float4 b = brow[lane + 32 * j];
        acc[j] = make_float4(a.x * dii + b.x, a.y * dii + b.y,
                             a.z * dii + b.z, a.w * dii + b.w);
    }
    int e0 = g_offs[i], e1 = g_offs[i + 1];
    for (int p = e0; p < e1; p++) {
        int   s  = g_csrc[p];
        float cf = g_ccoef[p];
        const float4* srow = (const float4*)(g_h + (size_t)s * Hh);
        #pragma unroll
        for (int j = 0; j < 4; j++) {
            float4 v = srow[lane + 32 * j];
            acc[j].x += v.x * cf; acc[j].y += v.y * cf;
            acc[j].z += v.z * cf; acc[j].w += v.w * cf;
        }
    }
    const float4* w1v = (const float4*)w1;
    const float4* w2v = (const float4*)w2;
    float4* orow = (float4*)(g_hr + (size_t)i * Hh);
    float p1 = 0.0f, p2 = 0.0f;
    #pragma unroll
    for (int j = 0; j < 4; j++) {
        acc[j].x = fmaxf(acc[j].x, 0.0f); acc[j].y = fmaxf(acc[j].y, 0.0f);
        acc[j].z = fmaxf(acc[j].z, 0.0f); acc[j].w = fmaxf(acc[j].w, 0.0f);
        orow[lane + 32 * j] = acc[j];
        float4 a = w1v[lane + 32 * j];
        float4 c = w2v[lane + 32 * j];
        p1 += acc[j].x * a.x + acc[j].y * a.y + acc[j].z * a.z + acc[j].w * a.w;
        p2 += acc[j].x * c.x + acc[j].y * c.y + acc[j].z * c.z + acc[j].w * c.w;
    }
    #pragma unroll
    for (int o = 16; o > 0; o >>= 1) {
        p1 += __shfl_down_sync(~0u, p1, o);
        p2 += __shfl_down_sync(~0u, p2, o);
    }
    if (lane == 0) { g_t1[i] = p1; g_t2[i] = p2; }
}

__global__ void k_score(const float* __restrict__ sagb) {
    int i = blockIdx.x * blockDim.x + threadIdx.x;
    if (i >= Nn) return;
    float s = g_t1[i] + sagb[0];
    int e0 = g_offs[i], e1 = g_offs[i + 1];
    for (int p = e0; p < e1; p++) s += g_t2[g_csrc[p]];
    g_score[i] = s;
}

__global__ __launch_bounds__(256) void k_topk() {
    __shared__ float sv[512];
    __shared__ int   si[512];
    int g = blockIdx.x, tid = threadIdx.x;
    #pragma unroll
    for (int t = tid; t < 512; t += 256) {
        if (t < NPG) { sv[t] = g_score[g * NPG + t]; si[t] = t; }
        else         { sv[t] = -INFINITY;            si[t] = -1; }
    }
    __syncthreads();
    for (int k = 2; k <= 512; k <<= 1) {
        for (int j = k >> 1; j > 0; j >>= 1) {
            #pragma unroll
            for (int t = tid; t < 512; t += 256) {
                int l = t ^ j;
                if (l > t) {
                    bool up = ((t & k) == 0);
                    float a = sv[t], b = sv[l];
                    if ((up && a > b) || (!up && a < b)) {
                        sv[t] = b; sv[l] = a;
                        int ia = si[t]; si[t] = si[l]; si[l] = ia;
                    }
                }
            }
            __syncthreads();
        }
    }
    if (tid < Kk) {
        int pos = 512 - Kk + tid;
        g_sel [g * Kk + tid] = g * NPG + si[pos];
        g_selw[g * Kk + tid] = tanhf(sv[pos]);
    }
}

__global__ __launch_bounds__(256) void k_pool() {
    __shared__ int   ssel[Kk];
    __shared__ float ssw [Kk];
    int g = blockIdx.x, t = threadIdx.x;
    for (int p = t; p < Kk; p += 256) {
        ssel[p] = g_sel [g * Kk + p];
        ssw [p] = g_selw[g * Kk + p];
    }
    __syncthreads();
    float a0 = 0, a1 = 0, q0 = 0, q1 = 0;
    for (int p = 0; p < Kk; p++) {
        const float* row = g_hr + (size_t)ssel[p] * Hh;
        float w  = ssw[p];
        float v0 = row[t]       * w;
        float v1 = row[t + 256] * w;
        a0 += v0; a1 += v1; q0 += v0 * v0; q1 += v1 * v1;
    }
    g_S [g * Hh + t]       = a0;
    g_S [g * Hh + t + 256] = a1;
    g_Qg[g * Hh + t]       = q0;
    g_Qg[g * Hh + t + 256] = q1;
}

__global__ void k_stats(const float* __restrict__ gamma, const float* __restrict__ beta) {
    int c = threadIdx.x;
    float sm = 0.0f, sq = 0.0f;
    for (int g = 0; g < Gg; g++) {
        sm += g_S [g * Hh + c];
        sq += g_Qg[g * Hh + c];
    }
    const float inv = 1.0f / (float)(Gg * Kk);
    float mu   = sm * inv;
    float var  = sq * inv - mu * mu;
    float rstd = rsqrtf(var + EPSBN);
    float sc   = rstd * gamma[c];
    g_A[c] = sc * (1.0f / (float)Kk);
    g_B[c] = beta[c] - mu * sc;
}

__global__ __launch_bounds__(128) void k_final(const float* __restrict__ fcw,
                                               const float* __restrict__ fcb,
                                               float* __restrict__ out) {
    int g = blockIdx.x, t = threadIdx.x;
    float lg[4] = {0, 0, 0, 0};
    for (int c = t; c < Hh; c += 128) {
        float p  = g_S[g * Hh + c] * g_A[c] + g_B[c];
        float4 w = *(const float4*)(fcw + c * Cc);
        lg[0] += p * w.x; lg[1] += p * w.y; lg[2] += p * w.z; lg[3] += p * w.w;
    }
    #pragma unroll
    for (int o = 16; o > 0; o >>= 1)
        #pragma unroll
        for (int k = 0; k < 4; k++) lg[k] += __shfl_down_sync(~0u, lg[k], o);
    __shared__ float sm[4][4];
    int lane = t & 31, w = t >> 5;
    if (lane == 0) { sm[w][0]=lg[0]; sm[w][1]=lg[1]; sm[w][2]=lg[2]; sm[w][3]=lg[3]; }
    __syncthreads();
    if (t == 0) {
        float l[4];
        #pragma unroll
        for (int k = 0; k < 4; k++)
            l[k] = sm[0][k] + sm[1][k] + sm[2][k] + sm[3][k] + fcb[k];
        float m = fmaxf(fmaxf(l[0], l[1]), fmaxf(l[2], l[3]));
        float s = 0.0f;
        #pragma unroll
        for (int k = 0; k < 4; k++) s += expf(l[k] - m);
        float lse = logf(s);
        #pragma unroll
        for (int k = 0; k < 4; k++) out[g * Cc + k] = l[k] - m - lse;
    }
}

// ---------------- launcher ----------------
extern "C" void kernel_launch(void* const* d_in, const int* in_sizes, int n_in,
                              void* d_out, int out_size) {
    const float* x     = (const float*)d_in[0];
    const float* gcnw  = (const float*)d_in[1];
    const float* gcnb  = (const float*)d_in[2];
    const float* sagw1 = (const float*)d_in[3];
    const float* sagw2 = (const float*)d_in[4];
    const float* sagb  = (const float*)d_in[5];
    const float* bngam = (const float*)d_in[6];
    const float* bnbet = (const float*)d_in[7];
    const float* fcw   = (const float*)d_in[8];
    const float* fcb   = (const float*)d_in[9];
    const void*  ei    = d_in[10];
    const int*   batw  = (const int*)d_in[11];
    float*       out   = (float*)d_out;

    cudaFuncSetAttribute(k_mma, cudaFuncAttributeMaxDynamicSharedMemorySize, MMA_SMEM);

    k_detect<<<1, 1>>>(batw);
    k_init <<<(Nn + 255) / 256, 256>>>();
    k_count<<<(Ee + 255) / 256, 256>>>(ei);
    k_dinv <<<(Nn + 255) / 256, 256>>>();
    k_scan <<<1, 1024>>>();
    k_fill <<<(Ee + 255) / 256, 256>>>(ei);

    k_conv_a<<<(int)(((size_t)Nn * DIN / 4 + 255) / 256), 256>>>(x);
    { dim3 gb(4, 48);
      k_conv_b<<<gb, 256>>>(gcnw); }

    { dim3 grid(2, Nn / 128);
      k_mma<<<grid, 256, MMA_SMEM>>>(); }

    k_agg  <<<(Nn * 32 + 255) / 256, 256>>>(gcnb, sagw1, sagw2);
    k_score<<<(Nn + 255) / 256, 256>>>(sagb);
    k_topk <<<Gg, 256>>>();
    k_pool <<<Gg, 256>>>();
    k_stats<<<1, Hh>>>(bngam, bnbet);
    k_final<<<Gg, 128>>>(fcw, fcb, out);
}